// round 4
// baseline (speedup 1.0000x reference)
#include <cuda_runtime.h>
#include <cstdint>

#define L  2
#define T  128
#define NB 64      // batch N
#define H  512
#define E  256
#define A  200
#define V  1000
#define S  40
#define LT (L*T)   // 256

// ---------------- scratch (device globals; no allocation allowed) ----------------
__device__ __align__(16) float g_Kproj[L*T*NB*A];    // (l,t,n,a)
__device__ __align__(16) float g_qproj[L*NB*A];      // (l,n,a)
__device__ __align__(16) float g_scores[NB*LT];      // (n, lt)
__device__ __align__(16) float g_x[(E+H)*NB];        // (k,n) transposed GRU0 input
__device__ __align__(16) float g_h[2][L][H*NB];      // [pingpong][layer][(k,n)]
__device__ __align__(16) float g_proj[H*NB];         // (k,n)
__device__ __align__(16) float g_part[2][4*H*NB];    // split-K partials

// ---------------- MUFU-free fast math ----------------
__device__ __forceinline__ float fast_rcp(float q) {
    float r = __uint_as_float(0x7EF311C3u - __float_as_uint(q));
    r = r * (2.0f - q * r);
    r = r * (2.0f - q * r);
    r = r * (2.0f - q * r);
    return r;
}

__device__ __forceinline__ float tanh_fast(float x) {
    const float c = 7.99881172180175781f;
    x = fminf(fmaxf(x, -c), c);
    float x2 = x * x;
    float p = fmaf(x2, -2.76076847742355e-16f, 2.00018790482477e-13f);
    p = fmaf(x2, p, -8.60467152213735e-11f);
    p = fmaf(x2, p,  5.12229709037114e-08f);
    p = fmaf(x2, p,  1.48572235717979e-05f);
    p = fmaf(x2, p,  6.37261928875436e-04f);
    p = fmaf(x2, p,  4.89352455891786e-03f);
    p = p * x;
    float q = fmaf(x2, 1.19825839466702e-06f, 1.18534705686654e-04f);
    q = fmaf(x2, q, 2.26843463243900e-03f);
    q = fmaf(x2, q, 4.89352518554385e-03f);
    return p * fast_rcp(q);
}

__device__ __forceinline__ float sigmoid_fast(float x) {
    return fmaf(tanh_fast(0.5f * x), 0.5f, 0.5f);
}

// ---------------- prep kernels ----------------
__global__ void prep_hinit(const float* __restrict__ efs) {
    int i = blockIdx.x * 256 + threadIdx.x;        // over L*NB*H
    if (i >= L * NB * H) return;
    int k = i % H;
    int n = (i / H) % NB;
    int l = i / (NB * H);
    g_h[0][l][k * NB + n] = efs[i];
}

// Kproj[l,tn,a] = sum_h eo[l,tn,h] * Kw[l,a,h] + Kb[l,a]
__global__ void kproj_gemm(const float* __restrict__ eo,
                           const float* __restrict__ Kw,
                           const float* __restrict__ Kb) {
    const int l   = blockIdx.z;
    const int tn0 = blockIdx.x * 64;
    const int a0  = blockIdx.y * 64;
    const float* Ab = eo + (size_t)l * (T * NB) * H;   // [8192,512]
    const float* Bb = Kw + (size_t)l * A * H;          // [200,512]
    __shared__ float As[16][64];
    __shared__ float Bs[16][64];
    const int tid = threadIdx.x;
    const int tr = tid >> 4, tc = tid & 15;
    const int lr = tid >> 2;             // 0..63
    const int lk = (tid & 3) * 4;        // 0,4,8,12
    float acc[4][4];
    #pragma unroll
    for (int i = 0; i < 4; i++)
        #pragma unroll
        for (int j = 0; j < 4; j++) acc[i][j] = 0.0f;

    for (int k0 = 0; k0 < H; k0 += 16) {
        float4 a4 = *reinterpret_cast<const float4*>(&Ab[(size_t)(tn0 + lr) * H + k0 + lk]);
        As[lk + 0][lr] = a4.x; As[lk + 1][lr] = a4.y;
        As[lk + 2][lr] = a4.z; As[lk + 3][lr] = a4.w;
        float4 b4 = make_float4(0.f, 0.f, 0.f, 0.f);
        if (a0 + lr < A)
            b4 = *reinterpret_cast<const float4*>(&Bb[(size_t)(a0 + lr) * H + k0 + lk]);
        Bs[lk + 0][lr] = b4.x; Bs[lk + 1][lr] = b4.y;
        Bs[lk + 2][lr] = b4.z; Bs[lk + 3][lr] = b4.w;
        __syncthreads();
        #pragma unroll
        for (int kk = 0; kk < 16; kk++) {
            float4 av = *reinterpret_cast<const float4*>(&As[kk][tr * 4]);
            float4 bv = *reinterpret_cast<const float4*>(&Bs[kk][tc * 4]);
            acc[0][0] = fmaf(av.x, bv.x, acc[0][0]);
            acc[0][1] = fmaf(av.x, bv.y, acc[0][1]);
            acc[0][2] = fmaf(av.x, bv.z, acc[0][2]);
            acc[0][3] = fmaf(av.x, bv.w, acc[0][3]);
            acc[1][0] = fmaf(av.y, bv.x, acc[1][0]);
            acc[1][1] = fmaf(av.y, bv.y, acc[1][1]);
            acc[1][2] = fmaf(av.y, bv.z, acc[1][2]);
            acc[1][3] = fmaf(av.y, bv.w, acc[1][3]);
            acc[2][0] = fmaf(av.z, bv.x, acc[2][0]);
            acc[2][1] = fmaf(av.z, bv.y, acc[2][1]);
            acc[2][2] = fmaf(av.z, bv.z, acc[2][2]);
            acc[2][3] = fmaf(av.z, bv.w, acc[2][3]);
            acc[3][0] = fmaf(av.w, bv.x, acc[3][0]);
            acc[3][1] = fmaf(av.w, bv.y, acc[3][1]);
            acc[3][2] = fmaf(av.w, bv.z, acc[3][2]);
            acc[3][3] = fmaf(av.w, bv.w, acc[3][3]);
        }
        __syncthreads();
    }
    #pragma unroll
    for (int i = 0; i < 4; i++) {
        int tn = tn0 + tr * 4 + i;
        #pragma unroll
        for (int j = 0; j < 4; j++) {
            int a = a0 + tc * 4 + j;
            if (a < A)
                g_Kproj[(size_t)(l * T * NB + tn) * A + a] = acc[i][j] + Kb[l * A + a];
        }
    }
}

// ---------------- per-step kernels ----------------

// qproj[l,n,a] = sum_k h[l,k,n] * Qw[l,a,k] + Qb[l,a]
// grid (25, L), block (16,8): tx -> n0=4*tx, ty -> a = bx*8+ty
__global__ void qproj_v2(const float* __restrict__ Qw,
                         const float* __restrict__ Qb, int cur) {
    int n0 = threadIdx.x * 4;
    int a  = blockIdx.x * 8 + threadIdx.y;
    int l  = blockIdx.y;
    const float* hp = g_h[cur][l];
    const float* w = Qw + ((size_t)l * A + a) * H;
    float acc[4] = {0.f, 0.f, 0.f, 0.f};
    #pragma unroll 2
    for (int k = 0; k < H; k += 4) {
        float4 wv = *reinterpret_cast<const float4*>(w + k);
        float4 h0 = *reinterpret_cast<const float4*>(&hp[(k + 0) * NB + n0]);
        float4 h1 = *reinterpret_cast<const float4*>(&hp[(k + 1) * NB + n0]);
        float4 h2 = *reinterpret_cast<const float4*>(&hp[(k + 2) * NB + n0]);
        float4 h3 = *reinterpret_cast<const float4*>(&hp[(k + 3) * NB + n0]);
        acc[0] = fmaf(wv.x, h0.x, acc[0]); acc[1] = fmaf(wv.x, h0.y, acc[1]);
        acc[2] = fmaf(wv.x, h0.z, acc[2]); acc[3] = fmaf(wv.x, h0.w, acc[3]);
        acc[0] = fmaf(wv.y, h1.x, acc[0]); acc[1] = fmaf(wv.y, h1.y, acc[1]);
        acc[2] = fmaf(wv.y, h1.z, acc[2]); acc[3] = fmaf(wv.y, h1.w, acc[3]);
        acc[0] = fmaf(wv.z, h2.x, acc[0]); acc[1] = fmaf(wv.z, h2.y, acc[1]);
        acc[2] = fmaf(wv.z, h2.z, acc[2]); acc[3] = fmaf(wv.z, h2.w, acc[3]);
        acc[0] = fmaf(wv.w, h3.x, acc[0]); acc[1] = fmaf(wv.w, h3.y, acc[1]);
        acc[2] = fmaf(wv.w, h3.z, acc[2]); acc[3] = fmaf(wv.w, h3.w, acc[3]);
    }
    float b = Qb[l * A + a];
    #pragma unroll
    for (int i = 0; i < 4; i++)
        g_qproj[((size_t)l * NB + n0 + i) * A + a] = acc[i] + b;
}

// scores[n, lt] = sum_a Vw[l,a]*tanh(qproj[l,n,a] + Kproj[l,t,n,a]) + Vb[l]
__global__ void scores_kernel(const float* __restrict__ Vw,
                              const float* __restrict__ Vb) {
    int t = blockIdx.x, l = blockIdx.y;
    int warp = threadIdx.x >> 5, lane = threadIdx.x & 31;
    int lt = l * T + t;
    const float* vw = Vw + l * A;
    float vb = Vb[l];
    for (int n = warp; n < NB; n += 8) {
        const float* kp = g_Kproj + (size_t)(lt * NB + n) * A;
        const float* qp = g_qproj + (size_t)(l * NB + n) * A;
        float acc = 0.f;
        for (int a = lane; a < A; a += 32)
            acc = fmaf(vw[a], tanh_fast(qp[a] + kp[a]), acc);
        #pragma unroll
        for (int o = 16; o > 0; o >>= 1)
            acc += __shfl_down_sync(0xFFFFFFFFu, acc, o);
        if (lane == 0) g_scores[n * LT + lt] = acc + vb;
    }
}

// Softmax over lt per n, context accumulation, plus embedding -> g_x (k,n).
__global__ void context_kernel(const float* __restrict__ eo,
                               const float* __restrict__ embW,
                               const int* __restrict__ targets, int s) {
    __shared__ float w[LT];
    __shared__ float red[128];
    int n = blockIdx.y;
    int hc = blockIdx.x;
    int tid = threadIdx.x;

    float s0 = g_scores[n * LT + tid];
    float s1 = g_scores[n * LT + tid + 128];
    red[tid] = fmaxf(s0, s1);
    __syncthreads();
    #pragma unroll
    for (int o = 64; o > 0; o >>= 1) {
        if (tid < o) red[tid] = fmaxf(red[tid], red[tid + o]);
        __syncthreads();
    }
    float mx = red[0];
    __syncthreads();
    float e0 = __expf(s0 - mx), e1 = __expf(s1 - mx);
    red[tid] = e0 + e1;
    __syncthreads();
    #pragma unroll
    for (int o = 64; o > 0; o >>= 1) {
        if (tid < o) red[tid] += red[tid + o];
        __syncthreads();
    }
    float inv = 1.0f / red[0];
    w[tid] = e0 * inv;
    w[tid + 128] = e1 * inv;
    __syncthreads();

    int h = hc * 128 + tid;
    const float* eop = eo + (size_t)n * H + h;     // stride NB*H between lt
    float acc = 0.f;
    #pragma unroll 8
    for (int lt = 0; lt < LT; lt++)
        acc = fmaf(w[lt], eop[(size_t)lt * (NB * H)], acc);
    g_x[(E + h) * NB + n] = acc;

    if (hc == 0) {
        int tok = (s == 0) ? 1 : targets[n * S + (s - 1)];
        for (int e = tid; e < E; e += 128)
            g_x[e * NB + n] = fmaxf(embW[tok * E + e], 0.0f);
    }
}

// GRU fused-K GEMM with split-K=2. Pointers resolved IN DEVICE CODE from selectors.
// LAYER==0: x = g_x (KIN=768), h = g_h[cur][0]. LAYER==1: x = g_h[cur^1][0], h = g_h[cur][1].
// grid (64, 2), block (16,8): tx -> 4n, ty -> j = bx*8+ty
template <int KIN, int LAYER>
__global__ void gru_gemm(const float* __restrict__ Wih,
                         const float* __restrict__ Whh, int cur) {
    constexpr int KTOT = KIN + H;
    constexpr int KHALF = KTOT / 2;
    int n0 = threadIdx.x * 4;
    int j  = blockIdx.x * 8 + threadIdx.y;
    int ks = blockIdx.y;
    int k0 = ks * KHALF, k1 = k0 + KHALF;

    const float* xin = (LAYER == 0) ? g_x : g_h[cur ^ 1][0];
    const float* hin = g_h[cur][LAYER];

    float ar[4] = {0,0,0,0}, az[4] = {0,0,0,0};
    float ai[4] = {0,0,0,0}, ah[4] = {0,0,0,0};

    // x segment: [k0, min(k1,KIN))
    {
        int ke = min(k1, KIN);
        const float* wr = Wih + (size_t)j * KIN;
        const float* wz = Wih + (size_t)(H + j) * KIN;
        const float* wn = Wih + (size_t)(2 * H + j) * KIN;
        #pragma unroll 2
        for (int k = k0; k < ke; k += 4) {
            float4 wR = *reinterpret_cast<const float4*>(wr + k);
            float4 wZ = *reinterpret_cast<const float4*>(wz + k);
            float4 wN = *reinterpret_cast<const float4*>(wn + k);
            float4 x0 = *reinterpret_cast<const float4*>(&xin[(k + 0) * NB + n0]);
            float4 x1 = *reinterpret_cast<const float4*>(&xin[(k + 1) * NB + n0]);
            float4 x2 = *reinterpret_cast<const float4*>(&xin[(k + 2) * NB + n0]);
            float4 x3 = *reinterpret_cast<const float4*>(&xin[(k + 3) * NB + n0]);
            ar[0]=fmaf(wR.x,x0.x,ar[0]); ar[1]=fmaf(wR.x,x0.y,ar[1]); ar[2]=fmaf(wR.x,x0.z,ar[2]); ar[3]=fmaf(wR.x,x0.w,ar[3]);
            ar[0]=fmaf(wR.y,x1.x,ar[0]); ar[1]=fmaf(wR.y,x1.y,ar[1]); ar[2]=fmaf(wR.y,x1.z,ar[2]); ar[3]=fmaf(wR.y,x1.w,ar[3]);
            ar[0]=fmaf(wR.z,x2.x,ar[0]); ar[1]=fmaf(wR.z,x2.y,ar[1]); ar[2]=fmaf(wR.z,x2.z,ar[2]); ar[3]=fmaf(wR.z,x2.w,ar[3]);
            ar[0]=fmaf(wR.w,x3.x,ar[0]); ar[1]=fmaf(wR.w,x3.y,ar[1]); ar[2]=fmaf(wR.w,x3.z,ar[2]); ar[3]=fmaf(wR.w,x3.w,ar[3]);
            az[0]=fmaf(wZ.x,x0.x,az[0]); az[1]=fmaf(wZ.x,x0.y,az[1]); az[2]=fmaf(wZ.x,x0.z,az[2]); az[3]=fmaf(wZ.x,x0.w,az[3]);
            az[0]=fmaf(wZ.y,x1.x,az[0]); az[1]=fmaf(wZ.y,x1.y,az[1]); az[2]=fmaf(wZ.y,x1.z,az[2]); az[3]=fmaf(wZ.y,x1.w,az[3]);
            az[0]=fmaf(wZ.z,x2.x,az[0]); az[1]=fmaf(wZ.z,x2.y,az[1]); az[2]=fmaf(wZ.z,x2.z,az[2]); az[3]=fmaf(wZ.z,x2.w,az[3]);
            az[0]=fmaf(wZ.w,x3.x,az[0]); az[1]=fmaf(wZ.w,x3.y,az[1]); az[2]=fmaf(wZ.w,x3.z,az[2]); az[3]=fmaf(wZ.w,x3.w,az[3]);
            ai[0]=fmaf(wN.x,x0.x,ai[0]); ai[1]=fmaf(wN.x,x0.y,ai[1]); ai[2]=fmaf(wN.x,x0.z,ai[2]); ai[3]=fmaf(wN.x,x0.w,ai[3]);
            ai[0]=fmaf(wN.y,x1.x,ai[0]); ai[1]=fmaf(wN.y,x1.y,ai[1]); ai[2]=fmaf(wN.y,x1.z,ai[2]); ai[3]=fmaf(wN.y,x1.w,ai[3]);
            ai[0]=fmaf(wN.z,x2.x,ai[0]); ai[1]=fmaf(wN.z,x2.y,ai[1]); ai[2]=fmaf(wN.z,x2.z,ai[2]); ai[3]=fmaf(wN.z,x2.w,ai[3]);
            ai[0]=fmaf(wN.w,x3.x,ai[0]); ai[1]=fmaf(wN.w,x3.y,ai[1]); ai[2]=fmaf(wN.w,x3.z,ai[2]); ai[3]=fmaf(wN.w,x3.w,ai[3]);
        }
    }
    // h segment: [max(k0,KIN)-KIN, k1-KIN)
    {
        int hs = max(k0, KIN) - KIN;
        int he = k1 - KIN;
        const float* wr = Whh + (size_t)j * H;
        const float* wz = Whh + (size_t)(H + j) * H;
        const float* wn = Whh + (size_t)(2 * H + j) * H;
        #pragma unroll 2
        for (int k = hs; k < he; k += 4) {
            float4 wR = *reinterpret_cast<const float4*>(wr + k);
            float4 wZ = *reinterpret_cast<const float4*>(wz + k);
            float4 wN = *reinterpret_cast<const float4*>(wn + k);
            float4 x0 = *reinterpret_cast<const float4*>(&hin[(k + 0) * NB + n0]);
            float4 x1 = *reinterpret_cast<const float4*>(&hin[(k + 1) * NB + n0]);
            float4 x2 = *reinterpret_cast<const float4*>(&hin[(k + 2) * NB + n0]);
            float4 x3 = *reinterpret_cast<const float4*>(&hin[(k + 3) * NB + n0]);
            ar[0]=fmaf(wR.x,x0.x,ar[0]); ar[1]=fmaf(wR.x,x0.y,ar[1]); ar[2]=fmaf(wR.x,x0.z,ar[2]); ar[3]=fmaf(wR.x,x0.w,ar[3]);
            ar[0]=fmaf(wR.y,x1.x,ar[0]); ar[1]=fmaf(wR.y,x1.y,ar[1]); ar[2]=fmaf(wR.y,x1.z,ar[2]); ar[3]=fmaf(wR.y,x1.w,ar[3]);
            ar[0]=fmaf(wR.z,x2.x,ar[0]); ar[1]=fmaf(wR.z,x2.y,ar[1]); ar[2]=fmaf(wR.z,x2.z,ar[2]); ar[3]=fmaf(wR.z,x2.w,ar[3]);
            ar[0]=fmaf(wR.w,x3.x,ar[0]); ar[1]=fmaf(wR.w,x3.y,ar[1]); ar[2]=fmaf(wR.w,x3.z,ar[2]); ar[3]=fmaf(wR.w,x3.w,ar[3]);
            az[0]=fmaf(wZ.x,x0.x,az[0]); az[1]=fmaf(wZ.x,x0.y,az[1]); az[2]=fmaf(wZ.x,x0.z,az[2]); az[3]=fmaf(wZ.x,x0.w,az[3]);
            az[0]=fmaf(wZ.y,x1.x,az[0]); az[1]=fmaf(wZ.y,x1.y,az[1]); az[2]=fmaf(wZ.y,x1.z,az[2]); az[3]=fmaf(wZ.y,x1.w,az[3]);
            az[0]=fmaf(wZ.z,x2.x,az[0]); az[1]=fmaf(wZ.z,x2.y,az[1]); az[2]=fmaf(wZ.z,x2.z,az[2]); az[3]=fmaf(wZ.z,x2.w,az[3]);
            az[0]=fmaf(wZ.w,x3.x,az[0]); az[1]=fmaf(wZ.w,x3.y,az[1]); az[2]=fmaf(wZ.w,x3.z,az[2]); az[3]=fmaf(wZ.w,x3.w,az[3]);
            ah[0]=fmaf(wN.x,x0.x,ah[0]); ah[1]=fmaf(wN.x,x0.y,ah[1]); ah[2]=fmaf(wN.x,x0.z,ah[2]); ah[3]=fmaf(wN.x,x0.w,ah[3]);
            ah[0]=fmaf(wN.y,x1.x,ah[0]); ah[1]=fmaf(wN.y,x1.y,ah[1]); ah[2]=fmaf(wN.y,x1.z,ah[2]); ah[3]=fmaf(wN.y,x1.w,ah[3]);
            ah[0]=fmaf(wN.z,x2.x,ah[0]); ah[1]=fmaf(wN.z,x2.y,ah[1]); ah[2]=fmaf(wN.z,x2.z,ah[2]); ah[3]=fmaf(wN.z,x2.w,ah[3]);
            ah[0]=fmaf(wN.w,x3.x,ah[0]); ah[1]=fmaf(wN.w,x3.y,ah[1]); ah[2]=fmaf(wN.w,x3.z,ah[2]); ah[3]=fmaf(wN.w,x3.w,ah[3]);
        }
    }
    float* p = g_part[ks];
    *reinterpret_cast<float4*>(&p[((size_t)0 * H + j) * NB + n0]) = make_float4(ar[0], ar[1], ar[2], ar[3]);
    *reinterpret_cast<float4*>(&p[((size_t)1 * H + j) * NB + n0]) = make_float4(az[0], az[1], az[2], az[3]);
    *reinterpret_cast<float4*>(&p[((size_t)2 * H + j) * NB + n0]) = make_float4(ai[0], ai[1], ai[2], ai[3]);
    *reinterpret_cast<float4*>(&p[((size_t)3 * H + j) * NB + n0]) = make_float4(ah[0], ah[1], ah[2], ah[3]);
}

// Combine split-K partials + GRU nonlinearity. grid 128, 256 thr.
__global__ void gru_gates(const float* __restrict__ bih,
                          const float* __restrict__ bhh,
                          int cur, int layer) {
    int idx = blockIdx.x * 256 + threadIdx.x;   // over H*NB
    int n = idx & (NB - 1);
    int j = idx >> 6;
    const float* hprev = g_h[cur][layer];
    float* hnew = g_h[cur ^ 1][layer];
    const float* p0 = g_part[0];
    const float* p1 = g_part[1];
    float ir = p0[(0 * H + j) * NB + n] + p1[(0 * H + j) * NB + n];
    float iz = p0[(1 * H + j) * NB + n] + p1[(1 * H + j) * NB + n];
    float ii = p0[(2 * H + j) * NB + n] + p1[(2 * H + j) * NB + n];
    float ih = p0[(3 * H + j) * NB + n] + p1[(3 * H + j) * NB + n];
    float r = sigmoid_fast(ir + bih[j] + bhh[j]);
    float z = sigmoid_fast(iz + bih[H + j] + bhh[H + j]);
    float nn = tanh_fast(ii + bih[2 * H + j] + r * (ih + bhh[2 * H + j]));
    float hp = hprev[j * NB + n];
    hnew[j * NB + n] = fmaf(z, hp - nn, nn);
}

// proj[j,n] = relu(sum_k h1[k,n]*Pw0[j,k] + Pb0[j]); grid 64, block (16,8)
__global__ void proj_v2(const float* __restrict__ Pw0,
                        const float* __restrict__ Pb0, int nxt) {
    int n0 = threadIdx.x * 4;
    int j  = blockIdx.x * 8 + threadIdx.y;
    const float* h1 = g_h[nxt][1];
    const float* w = Pw0 + (size_t)j * H;
    float acc[4] = {0.f, 0.f, 0.f, 0.f};
    #pragma unroll 2
    for (int k = 0; k < H; k += 4) {
        float4 wv = *reinterpret_cast<const float4*>(w + k);
        float4 h0 = *reinterpret_cast<const float4*>(&h1[(k + 0) * NB + n0]);
        float4 h1v = *reinterpret_cast<const float4*>(&h1[(k + 1) * NB + n0]);
        float4 h2 = *reinterpret_cast<const float4*>(&h1[(k + 2) * NB + n0]);
        float4 h3 = *reinterpret_cast<const float4*>(&h1[(k + 3) * NB + n0]);
        acc[0] = fmaf(wv.x, h0.x, acc[0]); acc[1] = fmaf(wv.x, h0.y, acc[1]);
        acc[2] = fmaf(wv.x, h0.z, acc[2]); acc[3] = fmaf(wv.x, h0.w, acc[3]);
        acc[0] = fmaf(wv.y, h1v.x, acc[0]); acc[1] = fmaf(wv.y, h1v.y, acc[1]);
        acc[2] = fmaf(wv.y, h1v.z, acc[2]); acc[3] = fmaf(wv.y, h1v.w, acc[3]);
        acc[0] = fmaf(wv.z, h2.x, acc[0]); acc[1] = fmaf(wv.z, h2.y, acc[1]);
        acc[2] = fmaf(wv.z, h2.z, acc[2]); acc[3] = fmaf(wv.z, h2.w, acc[3]);
        acc[0] = fmaf(wv.w, h3.x, acc[0]); acc[1] = fmaf(wv.w, h3.y, acc[1]);
        acc[2] = fmaf(wv.w, h3.z, acc[2]); acc[3] = fmaf(wv.w, h3.w, acc[3]);
    }
    float b = Pb0[j];
    float4 o;
    o.x = fmaxf(acc[0] + b, 0.f); o.y = fmaxf(acc[1] + b, 0.f);
    o.z = fmaxf(acc[2] + b, 0.f); o.w = fmaxf(acc[3] + b, 0.f);
    *reinterpret_cast<float4*>(&g_proj[(size_t)j * NB + n0]) = o;
}

// logits: out[n,s,v] = sum_k proj[k,n]*Pw1[v,k] + Pb1[v]; grid 125, block (16,8)
__global__ void logits_v2(const float* __restrict__ Pw1,
                          const float* __restrict__ Pb1,
                          float* __restrict__ out, int s) {
    int n0 = threadIdx.x * 4;
    int v  = blockIdx.x * 8 + threadIdx.y;
    const float* w = Pw1 + (size_t)v * H;
    float acc[4] = {0.f, 0.f, 0.f, 0.f};
    #pragma unroll 2
    for (int k = 0; k < H; k += 4) {
        float4 wv = *reinterpret_cast<const float4*>(w + k);
        float4 p0 = *reinterpret_cast<const float4*>(&g_proj[(k + 0) * NB + n0]);
        float4 p1 = *reinterpret_cast<const float4*>(&g_proj[(k + 1) * NB + n0]);
        float4 p2 = *reinterpret_cast<const float4*>(&g_proj[(k + 2) * NB + n0]);
        float4 p3 = *reinterpret_cast<const float4*>(&g_proj[(k + 3) * NB + n0]);
        acc[0] = fmaf(wv.x, p0.x, acc[0]); acc[1] = fmaf(wv.x, p0.y, acc[1]);
        acc[2] = fmaf(wv.x, p0.z, acc[2]); acc[3] = fmaf(wv.x, p0.w, acc[3]);
        acc[0] = fmaf(wv.y, p1.x, acc[0]); acc[1] = fmaf(wv.y, p1.y, acc[1]);
        acc[2] = fmaf(wv.y, p1.z, acc[2]); acc[3] = fmaf(wv.y, p1.w, acc[3]);
        acc[0] = fmaf(wv.z, p2.x, acc[0]); acc[1] = fmaf(wv.z, p2.y, acc[1]);
        acc[2] = fmaf(wv.z, p2.z, acc[2]); acc[3] = fmaf(wv.z, p2.w, acc[3]);
        acc[0] = fmaf(wv.w, p3.x, acc[0]); acc[1] = fmaf(wv.w, p3.y, acc[1]);
        acc[2] = fmaf(wv.w, p3.z, acc[2]); acc[3] = fmaf(wv.w, p3.w, acc[3]);
    }
    float b = Pb1[v];
    #pragma unroll
    for (int i = 0; i < 4; i++)
        out[((size_t)(n0 + i) * S + s) * V + v] = acc[i] + b;
}

// ---------------- launcher ----------------
extern "C" void kernel_launch(void* const* d_in, const int* in_sizes, int n_in,
                              void* d_out, int out_size) {
    const float* eo      = (const float*)d_in[0];
    const float* efs     = (const float*)d_in[1];
    const int*   targets = (const int*)  d_in[2];
    const float* embW    = (const float*)d_in[3];
    const float* Qw      = (const float*)d_in[4];
    const float* Qb      = (const float*)d_in[5];
    const float* Kw      = (const float*)d_in[6];
    const float* Kb      = (const float*)d_in[7];
    const float* Vw      = (const float*)d_in[8];
    const float* Vb      = (const float*)d_in[9];
    const float* Wih0    = (const float*)d_in[10];
    const float* Whh0    = (const float*)d_in[11];
    const float* bih0    = (const float*)d_in[12];
    const float* bhh0    = (const float*)d_in[13];
    const float* Wih1    = (const float*)d_in[14];
    const float* Whh1    = (const float*)d_in[15];
    const float* bih1    = (const float*)d_in[16];
    const float* bhh1    = (const float*)d_in[17];
    const float* Pw0     = (const float*)d_in[18];
    const float* Pb0     = (const float*)d_in[19];
    const float* Pw1     = (const float*)d_in[20];
    const float* Pb1     = (const float*)d_in[21];
    float* out = (float*)d_out;

    prep_hinit<<<(L * NB * H + 255) / 256, 256>>>(efs);
    kproj_gemm<<<dim3(128, 4, 2), 256>>>(eo, Kw, Kb);

    dim3 blk168(16, 8);
    for (int s = 0; s < S; s++) {
        int cur = s & 1;
        int nxt = cur ^ 1;
        qproj_v2<<<dim3(25, L), blk168>>>(Qw, Qb, cur);
        scores_kernel<<<dim3(T, L), 256>>>(Vw, Vb);
        context_kernel<<<dim3(4, NB), 128>>>(eo, embW, targets, s);
        gru_gemm<E + H, 0><<<dim3(64, 2), blk168>>>(Wih0, Whh0, cur);
        gru_gates<<<128, 256>>>(bih0, bhh0, cur, 0);
        gru_gemm<H, 1><<<dim3(64, 2), blk168>>>(Wih1, Whh1, cur);
        gru_gates<<<128, 256>>>(bih1, bhh1, cur, 1);
        proj_v2<<<64, blk168>>>(Pw0, Pb0, nxt);
        logits_v2<<<125, blk168>>>(Pw1, Pb1, out, s);
    }
}

// round 5
// speedup vs baseline: 1.7378x; 1.7378x over previous
#include <cuda_runtime.h>
#include <cstdint>

#define L  2
#define T  128
#define NB 64      // batch N
#define H  512
#define E  256
#define A  200
#define V  1000
#define S  40
#define LT (L*T)   // 256

// ---------------- scratch (device globals) ----------------
__device__ __align__(16) float g_Kproj[L*T*NB*A];    // (l,t,n,a)
__device__ __align__(16) float g_qpart[2][L*NB*A];   // qproj split-K partials (l,n,a)
__device__ __align__(16) float g_scores[NB*LT];      // (n, lt)
__device__ __align__(16) float g_x[(E+H)*NB];        // (k,n) transposed GRU0 input
__device__ __align__(16) float g_h[2][L][H*NB];      // [pingpong][layer][(k,n)]
__device__ __align__(16) float g_proj[H*NB];         // (k,n)
__device__ __align__(16) float g_part[4][4*H*NB];    // GRU split-K partials
__device__ __align__(16) float g_ppart[2][H*NB];     // proj split-K partials
__device__ __align__(16) float g_lpart[2][V*NB];     // logits split-K partials (v,n)

// ---------------- MUFU-free fast math ----------------
__device__ __forceinline__ float fast_rcp(float q) {
    float r = __uint_as_float(0x7EF311C3u - __float_as_uint(q));
    r = r * (2.0f - q * r);
    r = r * (2.0f - q * r);
    r = r * (2.0f - q * r);
    return r;
}

__device__ __forceinline__ float tanh_fast(float x) {
    const float c = 7.99881172180175781f;
    x = fminf(fmaxf(x, -c), c);
    float x2 = x * x;
    float p = fmaf(x2, -2.76076847742355e-16f, 2.00018790482477e-13f);
    p = fmaf(x2, p, -8.60467152213735e-11f);
    p = fmaf(x2, p,  5.12229709037114e-08f);
    p = fmaf(x2, p,  1.48572235717979e-05f);
    p = fmaf(x2, p,  6.37261928875436e-04f);
    p = fmaf(x2, p,  4.89352455891786e-03f);
    p = p * x;
    float q = fmaf(x2, 1.19825839466702e-06f, 1.18534705686654e-04f);
    q = fmaf(x2, q, 2.26843463243900e-03f);
    q = fmaf(x2, q, 4.89352518554385e-03f);
    return p * fast_rcp(q);
}

__device__ __forceinline__ float sigmoid_fast(float x) {
    return fmaf(tanh_fast(0.5f * x), 0.5f, 0.5f);
}

// ---------------- prep kernels ----------------
__global__ void prep_hinit(const float* __restrict__ efs) {
    int i = blockIdx.x * 256 + threadIdx.x;        // over L*NB*H
    if (i >= L * NB * H) return;
    int k = i % H;
    int n = (i / H) % NB;
    int l = i / (NB * H);
    g_h[0][l][k * NB + n] = efs[i];
}

__global__ void kproj_gemm(const float* __restrict__ eo,
                           const float* __restrict__ Kw,
                           const float* __restrict__ Kb) {
    const int l   = blockIdx.z;
    const int tn0 = blockIdx.x * 64;
    const int a0  = blockIdx.y * 64;
    const float* Ab = eo + (size_t)l * (T * NB) * H;
    const float* Bb = Kw + (size_t)l * A * H;
    __shared__ float As[16][64];
    __shared__ float Bs[16][64];
    const int tid = threadIdx.x;
    const int tr = tid >> 4, tc = tid & 15;
    const int lr = tid >> 2;
    const int lk = (tid & 3) * 4;
    float acc[4][4];
    #pragma unroll
    for (int i = 0; i < 4; i++)
        #pragma unroll
        for (int j = 0; j < 4; j++) acc[i][j] = 0.0f;

    for (int k0 = 0; k0 < H; k0 += 16) {
        float4 a4 = *reinterpret_cast<const float4*>(&Ab[(size_t)(tn0 + lr) * H + k0 + lk]);
        As[lk + 0][lr] = a4.x; As[lk + 1][lr] = a4.y;
        As[lk + 2][lr] = a4.z; As[lk + 3][lr] = a4.w;
        float4 b4 = make_float4(0.f, 0.f, 0.f, 0.f);
        if (a0 + lr < A)
            b4 = *reinterpret_cast<const float4*>(&Bb[(size_t)(a0 + lr) * H + k0 + lk]);
        Bs[lk + 0][lr] = b4.x; Bs[lk + 1][lr] = b4.y;
        Bs[lk + 2][lr] = b4.z; Bs[lk + 3][lr] = b4.w;
        __syncthreads();
        #pragma unroll
        for (int kk = 0; kk < 16; kk++) {
            float4 av = *reinterpret_cast<const float4*>(&As[kk][tr * 4]);
            float4 bv = *reinterpret_cast<const float4*>(&Bs[kk][tc * 4]);
            acc[0][0]=fmaf(av.x,bv.x,acc[0][0]); acc[0][1]=fmaf(av.x,bv.y,acc[0][1]);
            acc[0][2]=fmaf(av.x,bv.z,acc[0][2]); acc[0][3]=fmaf(av.x,bv.w,acc[0][3]);
            acc[1][0]=fmaf(av.y,bv.x,acc[1][0]); acc[1][1]=fmaf(av.y,bv.y,acc[1][1]);
            acc[1][2]=fmaf(av.y,bv.z,acc[1][2]); acc[1][3]=fmaf(av.y,bv.w,acc[1][3]);
            acc[2][0]=fmaf(av.z,bv.x,acc[2][0]); acc[2][1]=fmaf(av.z,bv.y,acc[2][1]);
            acc[2][2]=fmaf(av.z,bv.z,acc[2][2]); acc[2][3]=fmaf(av.z,bv.w,acc[2][3]);
            acc[3][0]=fmaf(av.w,bv.x,acc[3][0]); acc[3][1]=fmaf(av.w,bv.y,acc[3][1]);
            acc[3][2]=fmaf(av.w,bv.z,acc[3][2]); acc[3][3]=fmaf(av.w,bv.w,acc[3][3]);
        }
        __syncthreads();
    }
    #pragma unroll
    for (int i = 0; i < 4; i++) {
        int tn = tn0 + tr * 4 + i;
        #pragma unroll
        for (int j = 0; j < 4; j++) {
            int a = a0 + tc * 4 + j;
            if (a < A)
                g_Kproj[(size_t)(l * T * NB + tn) * A + a] = acc[i][j] + Kb[l * A + a];
        }
    }
}

// ---------------- per-step kernels ----------------

// qproj split-K=2: grid (25, L, 2), block (16,8). Partial (including bias in ks=0).
__global__ void qproj_v3(const float* __restrict__ Qw,
                         const float* __restrict__ Qb, int cur) {
    int n0 = threadIdx.x * 4;
    int a  = blockIdx.x * 8 + threadIdx.y;
    int l  = blockIdx.y;
    int ks = blockIdx.z;
    int k0 = ks * (H / 2), k1 = k0 + H / 2;
    const float* hp = g_h[cur][l];
    const float* w = Qw + ((size_t)l * A + a) * H;
    float acc[4] = {0.f, 0.f, 0.f, 0.f};
    #pragma unroll 4
    for (int k = k0; k < k1; k += 4) {
        float4 wv = *reinterpret_cast<const float4*>(w + k);
        float4 h0 = *reinterpret_cast<const float4*>(&hp[(k + 0) * NB + n0]);
        float4 h1 = *reinterpret_cast<const float4*>(&hp[(k + 1) * NB + n0]);
        float4 h2 = *reinterpret_cast<const float4*>(&hp[(k + 2) * NB + n0]);
        float4 h3 = *reinterpret_cast<const float4*>(&hp[(k + 3) * NB + n0]);
        acc[0]=fmaf(wv.x,h0.x,acc[0]); acc[1]=fmaf(wv.x,h0.y,acc[1]);
        acc[2]=fmaf(wv.x,h0.z,acc[2]); acc[3]=fmaf(wv.x,h0.w,acc[3]);
        acc[0]=fmaf(wv.y,h1.x,acc[0]); acc[1]=fmaf(wv.y,h1.y,acc[1]);
        acc[2]=fmaf(wv.y,h1.z,acc[2]); acc[3]=fmaf(wv.y,h1.w,acc[3]);
        acc[0]=fmaf(wv.z,h2.x,acc[0]); acc[1]=fmaf(wv.z,h2.y,acc[1]);
        acc[2]=fmaf(wv.z,h2.z,acc[2]); acc[3]=fmaf(wv.z,h2.w,acc[3]);
        acc[0]=fmaf(wv.w,h3.x,acc[0]); acc[1]=fmaf(wv.w,h3.y,acc[1]);
        acc[2]=fmaf(wv.w,h3.z,acc[2]); acc[3]=fmaf(wv.w,h3.w,acc[3]);
    }
    float b = (ks == 0) ? Qb[l * A + a] : 0.0f;
    float* dst = g_qpart[ks];
    #pragma unroll
    for (int i = 0; i < 4; i++)
        dst[((size_t)l * NB + n0 + i) * A + a] = acc[i] + b;
}

// scores: grid (T, L), block 512 = 16 warps; each warp handles 4 rows (MLP x4).
__global__ void scores_v3(const float* __restrict__ Vw,
                          const float* __restrict__ Vb) {
    int t = blockIdx.x, l = blockIdx.y;
    int warp = threadIdx.x >> 5, lane = threadIdx.x & 31;
    int lt = l * T + t;
    const float* vw = Vw + l * A;
    float vb = Vb[l];

    int n0 = warp, n1 = warp + 16, n2 = warp + 32, n3 = warp + 48;
    const float* kp0 = g_Kproj + (size_t)(lt * NB + n0) * A;
    const float* kp1 = g_Kproj + (size_t)(lt * NB + n1) * A;
    const float* kp2 = g_Kproj + (size_t)(lt * NB + n2) * A;
    const float* kp3 = g_Kproj + (size_t)(lt * NB + n3) * A;
    const float* qA = g_qpart[0] + (size_t)l * NB * A;
    const float* qB = g_qpart[1] + (size_t)l * NB * A;

    float a0 = 0.f, a1 = 0.f, a2 = 0.f, a3 = 0.f;
    for (int a = lane; a < A; a += 32) {
        float v = vw[a];
        float k0v = kp0[a], k1v = kp1[a], k2v = kp2[a], k3v = kp3[a];
        float q0 = qA[n0 * A + a] + qB[n0 * A + a];
        float q1 = qA[n1 * A + a] + qB[n1 * A + a];
        float q2 = qA[n2 * A + a] + qB[n2 * A + a];
        float q3 = qA[n3 * A + a] + qB[n3 * A + a];
        a0 = fmaf(v, tanh_fast(q0 + k0v), a0);
        a1 = fmaf(v, tanh_fast(q1 + k1v), a1);
        a2 = fmaf(v, tanh_fast(q2 + k2v), a2);
        a3 = fmaf(v, tanh_fast(q3 + k3v), a3);
    }
    #pragma unroll
    for (int o = 16; o > 0; o >>= 1) {
        a0 += __shfl_down_sync(0xFFFFFFFFu, a0, o);
        a1 += __shfl_down_sync(0xFFFFFFFFu, a1, o);
        a2 += __shfl_down_sync(0xFFFFFFFFu, a2, o);
        a3 += __shfl_down_sync(0xFFFFFFFFu, a3, o);
    }
    if (lane == 0) {
        g_scores[n0 * LT + lt] = a0 + vb;
        g_scores[n1 * LT + lt] = a1 + vb;
        g_scores[n2 * LT + lt] = a2 + vb;
        g_scores[n3 * LT + lt] = a3 + vb;
    }
}

// Softmax over lt per n, context accumulation, embedding -> g_x (k,n).
__global__ void context_kernel(const float* __restrict__ eo,
                               const float* __restrict__ embW,
                               const int* __restrict__ targets, int s) {
    __shared__ float w[LT];
    __shared__ float red[128];
    int n = blockIdx.y;
    int hc = blockIdx.x;
    int tid = threadIdx.x;

    float s0 = g_scores[n * LT + tid];
    float s1 = g_scores[n * LT + tid + 128];
    red[tid] = fmaxf(s0, s1);
    __syncthreads();
    #pragma unroll
    for (int o = 64; o > 0; o >>= 1) {
        if (tid < o) red[tid] = fmaxf(red[tid], red[tid + o]);
        __syncthreads();
    }
    float mx = red[0];
    __syncthreads();
    float e0 = __expf(s0 - mx), e1 = __expf(s1 - mx);
    red[tid] = e0 + e1;
    __syncthreads();
    #pragma unroll
    for (int o = 64; o > 0; o >>= 1) {
        if (tid < o) red[tid] += red[tid + o];
        __syncthreads();
    }
    float inv = 1.0f / red[0];
    w[tid] = e0 * inv;
    w[tid + 128] = e1 * inv;
    __syncthreads();

    int h = hc * 128 + tid;
    const float* eop = eo + (size_t)n * H + h;
    float acc = 0.f;
    #pragma unroll 16
    for (int lt = 0; lt < LT; lt++)
        acc = fmaf(w[lt], eop[(size_t)lt * (NB * H)], acc);
    g_x[(E + h) * NB + n] = acc;

    if (hc == 0) {
        int tok = (s == 0) ? 1 : targets[n * S + (s - 1)];
        for (int e = tid; e < E; e += 128)
            g_x[e * NB + n] = fmaxf(embW[tok * E + e], 0.0f);
    }
}

// GRU fused-K GEMM with split-K=4. grid (64, 4), block (16,8).
template <int KIN, int LAYER>
__global__ void gru_gemm(const float* __restrict__ Wih,
                         const float* __restrict__ Whh, int cur) {
    constexpr int KTOT = KIN + H;
    constexpr int KQ = KTOT / 4;
    int n0 = threadIdx.x * 4;
    int j  = blockIdx.x * 8 + threadIdx.y;
    int ks = blockIdx.y;
    int k0 = ks * KQ, k1 = k0 + KQ;

    const float* xin = (LAYER == 0) ? g_x : g_h[cur ^ 1][0];
    const float* hin = g_h[cur][LAYER];

    float ar[4] = {0,0,0,0}, az[4] = {0,0,0,0};
    float ai[4] = {0,0,0,0}, ah[4] = {0,0,0,0};

    // x segment: [k0, min(k1,KIN))
    {
        int ke = min(k1, KIN);
        const float* wr = Wih + (size_t)j * KIN;
        const float* wz = Wih + (size_t)(H + j) * KIN;
        const float* wn = Wih + (size_t)(2 * H + j) * KIN;
        #pragma unroll 2
        for (int k = k0; k < ke; k += 4) {
            float4 wR = *reinterpret_cast<const float4*>(wr + k);
            float4 wZ = *reinterpret_cast<const float4*>(wz + k);
            float4 wN = *reinterpret_cast<const float4*>(wn + k);
            float4 x0 = *reinterpret_cast<const float4*>(&xin[(k + 0) * NB + n0]);
            float4 x1 = *reinterpret_cast<const float4*>(&xin[(k + 1) * NB + n0]);
            float4 x2 = *reinterpret_cast<const float4*>(&xin[(k + 2) * NB + n0]);
            float4 x3 = *reinterpret_cast<const float4*>(&xin[(k + 3) * NB + n0]);
            ar[0]=fmaf(wR.x,x0.x,ar[0]); ar[1]=fmaf(wR.x,x0.y,ar[1]); ar[2]=fmaf(wR.x,x0.z,ar[2]); ar[3]=fmaf(wR.x,x0.w,ar[3]);
            ar[0]=fmaf(wR.y,x1.x,ar[0]); ar[1]=fmaf(wR.y,x1.y,ar[1]); ar[2]=fmaf(wR.y,x1.z,ar[2]); ar[3]=fmaf(wR.y,x1.w,ar[3]);
            ar[0]=fmaf(wR.z,x2.x,ar[0]); ar[1]=fmaf(wR.z,x2.y,ar[1]); ar[2]=fmaf(wR.z,x2.z,ar[2]); ar[3]=fmaf(wR.z,x2.w,ar[3]);
            ar[0]=fmaf(wR.w,x3.x,ar[0]); ar[1]=fmaf(wR.w,x3.y,ar[1]); ar[2]=fmaf(wR.w,x3.z,ar[2]); ar[3]=fmaf(wR.w,x3.w,ar[3]);
            az[0]=fmaf(wZ.x,x0.x,az[0]); az[1]=fmaf(wZ.x,x0.y,az[1]); az[2]=fmaf(wZ.x,x0.z,az[2]); az[3]=fmaf(wZ.x,x0.w,az[3]);
            az[0]=fmaf(wZ.y,x1.x,az[0]); az[1]=fmaf(wZ.y,x1.y,az[1]); az[2]=fmaf(wZ.y,x1.z,az[2]); az[3]=fmaf(wZ.y,x1.w,az[3]);
            az[0]=fmaf(wZ.z,x2.x,az[0]); az[1]=fmaf(wZ.z,x2.y,az[1]); az[2]=fmaf(wZ.z,x2.z,az[2]); az[3]=fmaf(wZ.z,x2.w,az[3]);
            az[0]=fmaf(wZ.w,x3.x,az[0]); az[1]=fmaf(wZ.w,x3.y,az[1]); az[2]=fmaf(wZ.w,x3.z,az[2]); az[3]=fmaf(wZ.w,x3.w,az[3]);
            ai[0]=fmaf(wN.x,x0.x,ai[0]); ai[1]=fmaf(wN.x,x0.y,ai[1]); ai[2]=fmaf(wN.x,x0.z,ai[2]); ai[3]=fmaf(wN.x,x0.w,ai[3]);
            ai[0]=fmaf(wN.y,x1.x,ai[0]); ai[1]=fmaf(wN.y,x1.y,ai[1]); ai[2]=fmaf(wN.y,x1.z,ai[2]); ai[3]=fmaf(wN.y,x1.w,ai[3]);
            ai[0]=fmaf(wN.z,x2.x,ai[0]); ai[1]=fmaf(wN.z,x2.y,ai[1]); ai[2]=fmaf(wN.z,x2.z,ai[2]); ai[3]=fmaf(wN.z,x2.w,ai[3]);
            ai[0]=fmaf(wN.w,x3.x,ai[0]); ai[1]=fmaf(wN.w,x3.y,ai[1]); ai[2]=fmaf(wN.w,x3.z,ai[2]); ai[3]=fmaf(wN.w,x3.w,ai[3]);
        }
    }
    // h segment
    {
        int hs = max(k0, KIN) - KIN;
        int he = k1 - KIN;
        const float* wr = Whh + (size_t)j * H;
        const float* wz = Whh + (size_t)(H + j) * H;
        const float* wn = Whh + (size_t)(2 * H + j) * H;
        #pragma unroll 2
        for (int k = hs; k < he; k += 4) {
            float4 wR = *reinterpret_cast<const float4*>(wr + k);
            float4 wZ = *reinterpret_cast<const float4*>(wz + k);
            float4 wN = *reinterpret_cast<const float4*>(wn + k);
            float4 x0 = *reinterpret_cast<const float4*>(&hin[(k + 0) * NB + n0]);
            float4 x1 = *reinterpret_cast<const float4*>(&hin[(k + 1) * NB + n0]);
            float4 x2 = *reinterpret_cast<const float4*>(&hin[(k + 2) * NB + n0]);
            float4 x3 = *reinterpret_cast<const float4*>(&hin[(k + 3) * NB + n0]);
            ar[0]=fmaf(wR.x,x0.x,ar[0]); ar[1]=fmaf(wR.x,x0.y,ar[1]); ar[2]=fmaf(wR.x,x0.z,ar[2]); ar[3]=fmaf(wR.x,x0.w,ar[3]);
            ar[0]=fmaf(wR.y,x1.x,ar[0]); ar[1]=fmaf(wR.y,x1.y,ar[1]); ar[2]=fmaf(wR.y,x1.z,ar[2]); ar[3]=fmaf(wR.y,x1.w,ar[3]);
            ar[0]=fmaf(wR.z,x2.x,ar[0]); ar[1]=fmaf(wR.z,x2.y,ar[1]); ar[2]=fmaf(wR.z,x2.z,ar[2]); ar[3]=fmaf(wR.z,x2.w,ar[3]);
            ar[0]=fmaf(wR.w,x3.x,ar[0]); ar[1]=fmaf(wR.w,x3.y,ar[1]); ar[2]=fmaf(wR.w,x3.z,ar[2]); ar[3]=fmaf(wR.w,x3.w,ar[3]);
            az[0]=fmaf(wZ.x,x0.x,az[0]); az[1]=fmaf(wZ.x,x0.y,az[1]); az[2]=fmaf(wZ.x,x0.z,az[2]); az[3]=fmaf(wZ.x,x0.w,az[3]);
            az[0]=fmaf(wZ.y,x1.x,az[0]); az[1]=fmaf(wZ.y,x1.y,az[1]); az[2]=fmaf(wZ.y,x1.z,az[2]); az[3]=fmaf(wZ.y,x1.w,az[3]);
            az[0]=fmaf(wZ.z,x2.x,az[0]); az[1]=fmaf(wZ.z,x2.y,az[1]); az[2]=fmaf(wZ.z,x2.z,az[2]); az[3]=fmaf(wZ.z,x2.w,az[3]);
            az[0]=fmaf(wZ.w,x3.x,az[0]); az[1]=fmaf(wZ.w,x3.y,az[1]); az[2]=fmaf(wZ.w,x3.z,az[2]); az[3]=fmaf(wZ.w,x3.w,az[3]);
            ah[0]=fmaf(wN.x,x0.x,ah[0]); ah[1]=fmaf(wN.x,x0.y,ah[1]); ah[2]=fmaf(wN.x,x0.z,ah[2]); ah[3]=fmaf(wN.x,x0.w,ah[3]);
            ah[0]=fmaf(wN.y,x1.x,ah[0]); ah[1]=fmaf(wN.y,x1.y,ah[1]); ah[2]=fmaf(wN.y,x1.z,ah[2]); ah[3]=fmaf(wN.y,x1.w,ah[3]);
            ah[0]=fmaf(wN.z,x2.x,ah[0]); ah[1]=fmaf(wN.z,x2.y,ah[1]); ah[2]=fmaf(wN.z,x2.z,ah[2]); ah[3]=fmaf(wN.z,x2.w,ah[3]);
            ah[0]=fmaf(wN.w,x3.x,ah[0]); ah[1]=fmaf(wN.w,x3.y,ah[1]); ah[2]=fmaf(wN.w,x3.z,ah[2]); ah[3]=fmaf(wN.w,x3.w,ah[3]);
        }
    }
    float* p = g_part[ks];
    *reinterpret_cast<float4*>(&p[((size_t)0 * H + j) * NB + n0]) = make_float4(ar[0], ar[1], ar[2], ar[3]);
    *reinterpret_cast<float4*>(&p[((size_t)1 * H + j) * NB + n0]) = make_float4(az[0], az[1], az[2], az[3]);
    *reinterpret_cast<float4*>(&p[((size_t)2 * H + j) * NB + n0]) = make_float4(ai[0], ai[1], ai[2], ai[3]);
    *reinterpret_cast<float4*>(&p[((size_t)3 * H + j) * NB + n0]) = make_float4(ah[0], ah[1], ah[2], ah[3]);
}

// Combine 4 split-K partials + GRU nonlinearity. grid 128, 256 thr.
__global__ void gru_gates(const float* __restrict__ bih,
                          const float* __restrict__ bhh,
                          int cur, int layer) {
    int idx = blockIdx.x * 256 + threadIdx.x;   // over H*NB
    int n = idx & (NB - 1);
    int j = idx >> 6;
    const float* hprev = g_h[cur][layer];
    float* hnew = g_h[cur ^ 1][layer];
    float ir = 0.f, iz = 0.f, ii = 0.f, ih = 0.f;
    #pragma unroll
    for (int ks = 0; ks < 4; ks++) {
        const float* p = g_part[ks];
        ir += p[(0 * H + j) * NB + n];
        iz += p[(1 * H + j) * NB + n];
        ii += p[(2 * H + j) * NB + n];
        ih += p[(3 * H + j) * NB + n];
    }
    float r = sigmoid_fast(ir + bih[j] + bhh[j]);
    float z = sigmoid_fast(iz + bih[H + j] + bhh[H + j]);
    float nn = tanh_fast(ii + bih[2 * H + j] + r * (ih + bhh[2 * H + j]));
    float hp = hprev[j * NB + n];
    hnew[j * NB + n] = fmaf(z, hp - nn, nn);
}

// proj GEMM split-K=2: grid (64,2), block (16,8)
__global__ void proj_gemm(const float* __restrict__ Pw0, int nxt) {
    int n0 = threadIdx.x * 4;
    int j  = blockIdx.x * 8 + threadIdx.y;
    int ks = blockIdx.y;
    int k0 = ks * (H / 2), k1 = k0 + H / 2;
    const float* h1 = g_h[nxt][1];
    const float* w = Pw0 + (size_t)j * H;
    float acc[4] = {0.f, 0.f, 0.f, 0.f};
    #pragma unroll 4
    for (int k = k0; k < k1; k += 4) {
        float4 wv = *reinterpret_cast<const float4*>(w + k);
        float4 h0 = *reinterpret_cast<const float4*>(&h1[(k + 0) * NB + n0]);
        float4 h1v = *reinterpret_cast<const float4*>(&h1[(k + 1) * NB + n0]);
        float4 h2 = *reinterpret_cast<const float4*>(&h1[(k + 2) * NB + n0]);
        float4 h3 = *reinterpret_cast<const float4*>(&h1[(k + 3) * NB + n0]);
        acc[0]=fmaf(wv.x,h0.x,acc[0]); acc[1]=fmaf(wv.x,h0.y,acc[1]);
        acc[2]=fmaf(wv.x,h0.z,acc[2]); acc[3]=fmaf(wv.x,h0.w,acc[3]);
        acc[0]=fmaf(wv.y,h1v.x,acc[0]); acc[1]=fmaf(wv.y,h1v.y,acc[1]);
        acc[2]=fmaf(wv.y,h1v.z,acc[2]); acc[3]=fmaf(wv.y,h1v.w,acc[3]);
        acc[0]=fmaf(wv.z,h2.x,acc[0]); acc[1]=fmaf(wv.z,h2.y,acc[1]);
        acc[2]=fmaf(wv.z,h2.z,acc[2]); acc[3]=fmaf(wv.z,h2.w,acc[3]);
        acc[0]=fmaf(wv.w,h3.x,acc[0]); acc[1]=fmaf(wv.w,h3.y,acc[1]);
        acc[2]=fmaf(wv.w,h3.z,acc[2]); acc[3]=fmaf(wv.w,h3.w,acc[3]);
    }
    *reinterpret_cast<float4*>(&g_ppart[ks][(size_t)j * NB + n0]) =
        make_float4(acc[0], acc[1], acc[2], acc[3]);
}

// relu(p0+p1+b) -> g_proj. 32768 el, grid 128 x 256.
__global__ void proj_combine(const float* __restrict__ Pb0) {
    int idx = blockIdx.x * 256 + threadIdx.x;
    int j = idx >> 6;
    float v = g_ppart[0][idx] + g_ppart[1][idx] + Pb0[j];
    g_proj[idx] = fmaxf(v, 0.0f);
}

// logits GEMM split-K=2: grid (125,2), block (16,8); partial (v,n)
__global__ void logits_gemm(const float* __restrict__ Pw1) {
    int n0 = threadIdx.x * 4;
    int v  = blockIdx.x * 8 + threadIdx.y;
    int ks = blockIdx.y;
    int k0 = ks * (H / 2), k1 = k0 + H / 2;
    const float* w = Pw1 + (size_t)v * H;
    float acc[4] = {0.f, 0.f, 0.f, 0.f};
    #pragma unroll 4
    for (int k = k0; k < k1; k += 4) {
        float4 wv = *reinterpret_cast<const float4*>(w + k);
        float4 p0 = *reinterpret_cast<const float4*>(&g_proj[(k + 0) * NB + n0]);
        float4 p1 = *reinterpret_cast<const float4*>(&g_proj[(k + 1) * NB + n0]);
        float4 p2 = *reinterpret_cast<const float4*>(&g_proj[(k + 2) * NB + n0]);
        float4 p3 = *reinterpret_cast<const float4*>(&g_proj[(k + 3) * NB + n0]);
        acc[0]=fmaf(wv.x,p0.x,acc[0]); acc[1]=fmaf(wv.x,p0.y,acc[1]);
        acc[2]=fmaf(wv.x,p0.z,acc[2]); acc[3]=fmaf(wv.x,p0.w,acc[3]);
        acc[0]=fmaf(wv.y,p1.x,acc[0]); acc[1]=fmaf(wv.y,p1.y,acc[1]);
        acc[2]=fmaf(wv.y,p1.z,acc[2]); acc[3]=fmaf(wv.y,p1.w,acc[3]);
        acc[0]=fmaf(wv.z,p2.x,acc[0]); acc[1]=fmaf(wv.z,p2.y,acc[1]);
        acc[2]=fmaf(wv.z,p2.z,acc[2]); acc[3]=fmaf(wv.z,p2.w,acc[3]);
        acc[0]=fmaf(wv.w,p3.x,acc[0]); acc[1]=fmaf(wv.w,p3.y,acc[1]);
        acc[2]=fmaf(wv.w,p3.z,acc[2]); acc[3]=fmaf(wv.w,p3.w,acc[3]);
    }
    *reinterpret_cast<float4*>(&g_lpart[ks][(size_t)v * NB + n0]) =
        make_float4(acc[0], acc[1], acc[2], acc[3]);
}

// out[n,s,v] = l0+l1+b. 64000 el, grid 250 x 256; v fastest for coalesced stores.
__global__ void logits_combine(const float* __restrict__ Pb1,
                               float* __restrict__ out, int s) {
    int idx = blockIdx.x * 256 + threadIdx.x;
    int n = idx / V;
    int v = idx - n * V;
    float r = g_lpart[0][(size_t)v * NB + n] + g_lpart[1][(size_t)v * NB + n] + Pb1[v];
    out[((size_t)n * S + s) * V + v] = r;
}

// ---------------- launcher ----------------
extern "C" void kernel_launch(void* const* d_in, const int* in_sizes, int n_in,
                              void* d_out, int out_size) {
    const float* eo      = (const float*)d_in[0];
    const float* efs     = (const float*)d_in[1];
    const int*   targets = (const int*)  d_in[2];
    const float* embW    = (const float*)d_in[3];
    const float* Qw      = (const float*)d_in[4];
    const float* Qb      = (const float*)d_in[5];
    const float* Kw      = (const float*)d_in[6];
    const float* Kb      = (const float*)d_in[7];
    const float* Vw      = (const float*)d_in[8];
    const float* Vb      = (const float*)d_in[9];
    const float* Wih0    = (const float*)d_in[10];
    const float* Whh0    = (const float*)d_in[11];
    const float* bih0    = (const float*)d_in[12];
    const float* bhh0    = (const float*)d_in[13];
    const float* Wih1    = (const float*)d_in[14];
    const float* Whh1    = (const float*)d_in[15];
    const float* bih1    = (const float*)d_in[16];
    const float* bhh1    = (const float*)d_in[17];
    const float* Pw0     = (const float*)d_in[18];
    const float* Pb0     = (const float*)d_in[19];
    const float* Pw1     = (const float*)d_in[20];
    const float* Pb1     = (const float*)d_in[21];
    float* out = (float*)d_out;

    prep_hinit<<<(L * NB * H + 255) / 256, 256>>>(efs);
    kproj_gemm<<<dim3(128, 4, 2), 256>>>(eo, Kw, Kb);

    dim3 blk168(16, 8);
    for (int s = 0; s < S; s++) {
        int cur = s & 1;
        int nxt = cur ^ 1;
        qproj_v3<<<dim3(25, L, 2), blk168>>>(Qw, Qb, cur);
        scores_v3<<<dim3(T, L), 512>>>(Vw, Vb);
        context_kernel<<<dim3(4, NB), 128>>>(eo, embW, targets, s);
        gru_gemm<E + H, 0><<<dim3(64, 4), blk168>>>(Wih0, Whh0, cur);
        gru_gates<<<128, 256>>>(bih0, bhh0, cur, 0);
        gru_gemm<H, 1><<<dim3(64, 4), blk168>>>(Wih1, Whh1, cur);
        gru_gates<<<128, 256>>>(bih1, bhh1, cur, 1);
        proj_gemm<<<dim3(64, 2), blk168>>>(Pw0, nxt);
        proj_combine<<<128, 256>>>(Pb0);
        logits_gemm<<<dim3(125, 2), blk168>>>(Pw1);
        logits_combine<<<250, 256>>>(Pb1, out, s);
    }
}